// round 1
// baseline (speedup 1.0000x reference)
#include <cuda_runtime.h>

#define SQ     192
#define DMODEL 512
#define NH     8
#define DHEAD  64

// Scratch (allocation-free rule: __device__ globals)
__device__ float g_q [NH*SQ*DHEAD];
__device__ float g_k0[NH*SQ*DHEAD];
__device__ float g_k1[NH*SQ*DHEAD];
__device__ float g_v0[NH*SQ*DHEAD];
__device__ float g_v1[NH*SQ*DHEAD];
__device__ float g_att[SQ*DMODEL];

// ---------------------------------------------------------------------------
// Projection: Y = X @ W^T + b.  X:[192,512], W:[512,512] (out,in), b:[512].
// sel 0..4: X=Xext, store split by head into g_q/g_k0/g_k1/g_v0/g_v1 as [H][S][DK]
// sel 5   : X=g_att, store plain [S][DM] into Yext (final output GEMM)
// Tiling: 64x64 output tile, K-chunks of 16, 4x4 register tile, 256 threads.
// ---------------------------------------------------------------------------
__global__ void proj_kernel(const float* __restrict__ Xext,
                            const float* __restrict__ W,
                            const float* __restrict__ bias,
                            float* __restrict__ Yext,
                            int sel)
{
    __shared__ float sx[64][17];
    __shared__ float sw[64][17];

    const float* X;
    float* Y;
    int split;
    if (sel == 5) { X = g_att; Y = Yext; split = 0; }
    else {
        X = Xext; split = 1;
        switch (sel) {
            case 0:  Y = g_q;  break;
            case 1:  Y = g_k0; break;
            case 2:  Y = g_k1; break;
            case 3:  Y = g_v0; break;
            default: Y = g_v1; break;
        }
    }

    const int bs = blockIdx.x * 64;   // row (s) tile
    const int bo = blockIdx.y * 64;   // col (o) tile
    const int tx = threadIdx.x & 15;
    const int ty = threadIdx.x >> 4;

    float acc[4][4] = {};

    for (int kk0 = 0; kk0 < DMODEL; kk0 += 16) {
        for (int e = threadIdx.x; e < 1024; e += 256) {
            int kk = e & 15, r = e >> 4;
            sx[r][kk] = X[(bs + r) * DMODEL + kk0 + kk];
            sw[r][kk] = W[(bo + r) * DMODEL + kk0 + kk];
        }
        __syncthreads();
        #pragma unroll
        for (int kk = 0; kk < 16; kk++) {
            float a[4], b[4];
            #pragma unroll
            for (int i = 0; i < 4; i++) a[i] = sx[ty*4 + i][kk];
            #pragma unroll
            for (int j = 0; j < 4; j++) b[j] = sw[tx*4 + j][kk];
            #pragma unroll
            for (int i = 0; i < 4; i++)
                #pragma unroll
                for (int j = 0; j < 4; j++)
                    acc[i][j] = fmaf(a[i], b[j], acc[i][j]);
        }
        __syncthreads();
    }

    #pragma unroll
    for (int i = 0; i < 4; i++) {
        int s = bs + ty*4 + i;
        #pragma unroll
        for (int j = 0; j < 4; j++) {
            int o = bo + tx*4 + j;
            float v = acc[i][j] + bias[o];
            if (split) Y[(o >> 6) * (SQ*DHEAD) + s * DHEAD + (o & 63)] = v;
            else       Y[s * DMODEL + o] = v;
        }
    }
}

// ---------------------------------------------------------------------------
// Attention core: one CTA per (h, k).  256 threads.
//   S[l,m] = scale * sum_d q[k,d]*k0[l,d]*k1[m,d]   (GEMM1, scores in SMEM)
//   p = softmax_m(S)                                 (in-place in SMEM)
//   out[d] = sum_l v0[l,d] * (sum_m p[l,m]*v1[m,d])  (GEMM2 + reduce)
// SMEM: sc[192*192] + two 64x65 staging tiles + qsc[64] + sout[64] = 181 KB.
// ---------------------------------------------------------------------------
__global__ __launch_bounds__(256, 1)
void attn_kernel()
{
    extern __shared__ float smem[];
    float* sc   = smem;                 // 192*192 scores / probs
    float* ta   = sc + SQ*SQ;           // 64*65  (A tile, [d][l], padded)
    float* tb   = ta + 64*65;           // 64*65  (B tile)
    float* qsc  = tb + 64*65;           // 64     q row * scale
    float* sout = qsc + 64;             // 64     output accumulator

    const int k   = blockIdx.x;
    const int h   = blockIdx.y;
    const int tid = threadIdx.x;
    const int tx  = tid & 15;
    const int ty  = tid >> 4;

    const float* qp  = g_q  + (h*SQ + k) * DHEAD;
    const float* k0p = g_k0 + h*SQ*DHEAD;
    const float* k1p = g_k1 + h*SQ*DHEAD;
    const float* v0p = g_v0 + h*SQ*DHEAD;
    const float* v1p = g_v1 + h*SQ*DHEAD;

    if (tid < 64) { qsc[tid] = qp[tid] * 0.125f; sout[tid] = 0.0f; }
    __syncthreads();

    // ---------------- GEMM1: sc[l,m] = (qsc .* k0) @ k1^T ----------------
    for (int lt = 0; lt < 3; lt++) {
        // stage A tile transposed: ta[d][i] = qsc[d] * k0[lt*64+i][d]
        for (int e = tid; e < 4096; e += 256) {
            int d = e & 63, i = e >> 6;
            ta[d*65 + i] = qsc[d] * k0p[(lt*64 + i)*DHEAD + d];
        }
        for (int mt = 0; mt < 3; mt++) {
            for (int e = tid; e < 4096; e += 256) {
                int d = e & 63, i = e >> 6;
                tb[d*65 + i] = k1p[(mt*64 + i)*DHEAD + d];
            }
            __syncthreads();
            float acc[4][4] = {};
            #pragma unroll 8
            for (int d = 0; d < 64; d++) {
                float a[4], b[4];
                #pragma unroll
                for (int i = 0; i < 4; i++) a[i] = ta[d*65 + ty*4 + i];
                #pragma unroll
                for (int j = 0; j < 4; j++) b[j] = tb[d*65 + tx*4 + j];
                #pragma unroll
                for (int i = 0; i < 4; i++)
                    #pragma unroll
                    for (int j = 0; j < 4; j++)
                        acc[i][j] = fmaf(a[i], b[j], acc[i][j]);
            }
            #pragma unroll
            for (int i = 0; i < 4; i++)
                #pragma unroll
                for (int j = 0; j < 4; j++)
                    sc[(lt*64 + ty*4 + i)*SQ + mt*64 + tx*4 + j] = acc[i][j];
            __syncthreads();
        }
    }

    // ---------------- softmax over m (rows of sc) ----------------
    {
        const int warp = tid >> 5, lane = tid & 31;
        for (int l = warp; l < SQ; l += 8) {
            float* row = sc + l*SQ;
            float mx = -1e30f;
            for (int m = lane; m < SQ; m += 32) mx = fmaxf(mx, row[m]);
            #pragma unroll
            for (int o = 16; o; o >>= 1)
                mx = fmaxf(mx, __shfl_xor_sync(0xffffffffu, mx, o));
            float sum = 0.0f;
            for (int m = lane; m < SQ; m += 32) {
                float e = __expf(row[m] - mx);
                row[m] = e;
                sum += e;
            }
            #pragma unroll
            for (int o = 16; o; o >>= 1)
                sum += __shfl_xor_sync(0xffffffffu, sum, o);
            float inv = 1.0f / sum;
            for (int m = lane; m < SQ; m += 32) row[m] *= inv;
        }
        __syncthreads();
    }

    // ---------------- GEMM2: u = p @ v1, out[d] += v0[l,d]*u[l,d] ----------------
    for (int lt = 0; lt < 3; lt++) {
        float acc[4][4] = {};
        for (int mt = 0; mt < 3; mt++) {
            for (int e = tid; e < 4096; e += 256) {
                int d = e & 63, mm = e >> 6;
                tb[mm*65 + d] = v1p[(mt*64 + mm)*DHEAD + d];
            }
            __syncthreads();
            #pragma unroll 8
            for (int mm = 0; mm < 64; mm++) {
                float a[4], b[4];
                #pragma unroll
                for (int j = 0; j < 4; j++) b[j] = tb[mm*65 + tx*4 + j];
                #pragma unroll
                for (int i = 0; i < 4; i++)
                    a[i] = sc[(lt*64 + ty*4 + i)*SQ + mt*64 + mm];
                #pragma unroll
                for (int i = 0; i < 4; i++)
                    #pragma unroll
                    for (int j = 0; j < 4; j++)
                        acc[i][j] = fmaf(a[i], b[j], acc[i][j]);
            }
            __syncthreads();
        }
        float part[4] = {};
        #pragma unroll
        for (int i = 0; i < 4; i++) {
            int l = lt*64 + ty*4 + i;
            #pragma unroll
            for (int j = 0; j < 4; j++)
                part[j] += acc[i][j] * v0p[l*DHEAD + tx*4 + j];
        }
        #pragma unroll
        for (int j = 0; j < 4; j++) atomicAdd(&sout[tx*4 + j], part[j]);
    }
    __syncthreads();
    if (tid < 64) g_att[k*DMODEL + h*DHEAD + tid] = sout[tid];
}

// ---------------------------------------------------------------------------
extern "C" void kernel_launch(void* const* d_in, const int* in_sizes, int n_in,
                              void* d_out, int out_size)
{
    (void)in_sizes; (void)n_in; (void)out_size;

    const float* query = (const float*)d_in[0];
    const float* key   = (const float*)d_in[1];
    const float* value = (const float*)d_in[2];
    const float* Wq    = (const float*)d_in[3];
    const float* bq    = (const float*)d_in[4];
    const float* Wk0   = (const float*)d_in[5];
    const float* bk0   = (const float*)d_in[6];
    const float* Wk1   = (const float*)d_in[7];
    const float* bk1   = (const float*)d_in[8];
    const float* Wv0   = (const float*)d_in[9];
    const float* bv0   = (const float*)d_in[10];
    const float* Wv1   = (const float*)d_in[11];
    const float* bv1   = (const float*)d_in[12];
    const float* Wo    = (const float*)d_in[13];
    const float* bo    = (const float*)d_in[14];
    float* out = (float*)d_out;

    const size_t attn_smem = (size_t)(SQ*SQ + 2*64*65 + 128) * sizeof(float); // 181248 B
    cudaFuncSetAttribute(attn_kernel,
                         cudaFuncAttributeMaxDynamicSharedMemorySize,
                         (int)attn_smem);

    dim3 pg(3, 8);
    proj_kernel<<<pg, 256>>>(query, Wq,  bq,  nullptr, 0);
    proj_kernel<<<pg, 256>>>(key,   Wk0, bk0, nullptr, 1);
    proj_kernel<<<pg, 256>>>(key,   Wk1, bk1, nullptr, 2);
    proj_kernel<<<pg, 256>>>(value, Wv0, bv0, nullptr, 3);
    proj_kernel<<<pg, 256>>>(value, Wv1, bv1, nullptr, 4);

    attn_kernel<<<dim3(SQ, NH), 256, attn_smem>>>();

    proj_kernel<<<pg, 256>>>(nullptr, Wo, bo, out, 5);
}

// round 2
// speedup vs baseline: 1.7734x; 1.7734x over previous
#include <cuda_runtime.h>

#define SQ     192
#define DM     512
#define NH     8
#define DK     64
#define SCST   196   // scores row stride (floats), 16B-aligned blocks

// Scratch (allocation-free rule: __device__ globals)
__device__ float g_q [NH*SQ*DK];
__device__ float g_k0[NH*SQ*DK];
__device__ float g_k1[NH*SQ*DK];
__device__ float g_v0[NH*SQ*DK];
__device__ float g_v1[NH*SQ*DK];
__device__ float g_att[SQ*DM];

// ---------------------------------------------------------------------------
// Projection: Y = X @ W^T + b.  X:[192,512], W:[512,512] (out,in).
// sel 0..4 : split per head -> g_* as [H][S][DK]. sel 5: final, plain [S][DM].
// 64x64 tile, K-chunk 32, float4 LDG + register double buffer,
// transposed SMEM staging -> inner loop = 2x LDS.128 + 16 FFMA.
// ---------------------------------------------------------------------------
__global__ __launch_bounds__(256) void proj_kernel(
    const float* __restrict__ query, const float* __restrict__ keyi,
    const float* __restrict__ value,
    const float* __restrict__ Wq,  const float* __restrict__ bq,
    const float* __restrict__ Wk0, const float* __restrict__ bk0,
    const float* __restrict__ Wk1, const float* __restrict__ bk1,
    const float* __restrict__ Wv0, const float* __restrict__ bv0,
    const float* __restrict__ Wv1, const float* __restrict__ bv1,
    const float* __restrict__ Wo,  const float* __restrict__ bo,
    float* __restrict__ out, int base_sel)
{
    __shared__ __align__(16) float sx[32*68];
    __shared__ __align__(16) float sw[32*68];

    const int sel = base_sel + blockIdx.z;
    const float *X, *W, *B; float* Y; int split = 1;
    switch (sel) {
        case 0:  X = query; W = Wq;  B = bq;  Y = g_q;  break;
        case 1:  X = keyi;  W = Wk0; B = bk0; Y = g_k0; break;
        case 2:  X = keyi;  W = Wk1; B = bk1; Y = g_k1; break;
        case 3:  X = value; W = Wv0; B = bv0; Y = g_v0; break;
        case 4:  X = value; W = Wv1; B = bv1; Y = g_v1; break;
        default: X = g_att; W = Wo;  B = bo;  Y = out;  split = 0; break;
    }

    const int bs  = blockIdx.x * 64;   // row (s) tile
    const int bo_ = blockIdx.y * 64;   // col (o) tile
    const int tid = threadIdx.x;
    const int tx  = tid & 15;
    const int ty  = tid >> 4;

    float4 px[2], pw[2];
    #pragma unroll
    for (int u = 0; u < 2; u++) {
        int e = tid + u*256, c4 = e >> 6, r = e & 63;
        px[u] = *(const float4*)&X[(bs  + r)*DM + c4*4];
        pw[u] = *(const float4*)&W[(bo_ + r)*DM + c4*4];
    }

    float acc[4][4] = {};

    for (int ch = 0; ch < 16; ch++) {
        #pragma unroll
        for (int u = 0; u < 2; u++) {
            int e = tid + u*256, c4 = e >> 6, r = e & 63;
            float* dx = &sx[(c4*4)*68 + r];
            dx[0] = px[u].x; dx[68] = px[u].y; dx[136] = px[u].z; dx[204] = px[u].w;
            float* dw = &sw[(c4*4)*68 + r];
            dw[0] = pw[u].x; dw[68] = pw[u].y; dw[136] = pw[u].z; dw[204] = pw[u].w;
        }
        __syncthreads();
        if (ch < 15) {
            #pragma unroll
            for (int u = 0; u < 2; u++) {
                int e = tid + u*256, c4 = e >> 6, r = e & 63;
                px[u] = *(const float4*)&X[(bs  + r)*DM + (ch+1)*32 + c4*4];
                pw[u] = *(const float4*)&W[(bo_ + r)*DM + (ch+1)*32 + c4*4];
            }
        }
        #pragma unroll
        for (int kk = 0; kk < 32; kk++) {
            float4 av = *(const float4*)&sx[kk*68 + ty*4];
            float4 bv = *(const float4*)&sw[kk*68 + tx*4];
            acc[0][0] = fmaf(av.x, bv.x, acc[0][0]);
            acc[0][1] = fmaf(av.x, bv.y, acc[0][1]);
            acc[0][2] = fmaf(av.x, bv.z, acc[0][2]);
            acc[0][3] = fmaf(av.x, bv.w, acc[0][3]);
            acc[1][0] = fmaf(av.y, bv.x, acc[1][0]);
            acc[1][1] = fmaf(av.y, bv.y, acc[1][1]);
            acc[1][2] = fmaf(av.y, bv.z, acc[1][2]);
            acc[1][3] = fmaf(av.y, bv.w, acc[1][3]);
            acc[2][0] = fmaf(av.z, bv.x, acc[2][0]);
            acc[2][1] = fmaf(av.z, bv.y, acc[2][1]);
            acc[2][2] = fmaf(av.z, bv.z, acc[2][2]);
            acc[2][3] = fmaf(av.z, bv.w, acc[2][3]);
            acc[3][0] = fmaf(av.w, bv.x, acc[3][0]);
            acc[3][1] = fmaf(av.w, bv.y, acc[3][1]);
            acc[3][2] = fmaf(av.w, bv.z, acc[3][2]);
            acc[3][3] = fmaf(av.w, bv.w, acc[3][3]);
        }
        __syncthreads();
    }

    const int o4 = bo_ + tx*4;
    float4 bb = *(const float4*)&B[o4];
    #pragma unroll
    for (int i = 0; i < 4; i++) {
        int s = bs + ty*4 + i;
        float4 r;
        r.x = acc[i][0] + bb.x; r.y = acc[i][1] + bb.y;
        r.z = acc[i][2] + bb.z; r.w = acc[i][3] + bb.w;
        if (split) *(float4*)&Y[(o4 >> 6)*(SQ*DK) + s*DK + (o4 & 63)] = r;
        else       *(float4*)&Y[s*DM + o4] = r;
    }
}

// ---------------------------------------------------------------------------
// Attention core: one CTA per (h, k), 256 threads, 2 CTAs/SM.
// l-blocked: per 64 l-rows -> scores block 64x192 in SMEM, softmax, GEMM2,
// v0-reduction accumulated in registers across l-blocks.
// SMEM: 64*196 + 2*64*68 + 128 floats = 85.5 KB.
// ---------------------------------------------------------------------------
__global__ __launch_bounds__(256, 2)
void attn_kernel()
{
    extern __shared__ __align__(16) float smem[];
    float* scb  = smem;                 // [64][SCST] scores / probs block
    float* ta   = scb + 64*SCST;        // [64][68]  (d-major A tile)
    float* tb   = ta  + 64*68;          // [64][68]
    float* qsc  = tb  + 64*68;          // [64]
    float* sout = qsc + 64;             // [64]

    const int k   = blockIdx.x;
    const int h   = blockIdx.y;
    const int tid = threadIdx.x;
    const int tx  = tid & 15;
    const int ty  = tid >> 4;
    const int warp = tid >> 5, lane = tid & 31;

    const float* qp  = g_q  + (h*SQ + k) * DK;
    const float* k0p = g_k0 + h*SQ*DK;
    const float* k1p = g_k1 + h*SQ*DK;
    const float* v0p = g_v0 + h*SQ*DK;
    const float* v1p = g_v1 + h*SQ*DK;

    if (tid < 64) { qsc[tid] = qp[tid] * 0.125f; sout[tid] = 0.0f; }
    __syncthreads();

    float part[4] = {};

    for (int lt = 0; lt < 3; lt++) {
        // stage ta[d][i] = qsc[d] * k0[lt*64+i][d]
        for (int e = tid; e < 4096; e += 256) {
            int d = e & 63, i = e >> 6;
            ta[d*68 + i] = qsc[d] * k0p[(lt*64 + i)*DK + d];
        }

        // ---- GEMM1: scb[i, mt*64+j] = sum_d ta[d][i]*tb[d][j] ----
        for (int mt = 0; mt < 3; mt++) {
            for (int e = tid; e < 4096; e += 256) {
                int d = e & 63, j = e >> 6;
                tb[d*68 + j] = k1p[(mt*64 + j)*DK + d];
            }
            __syncthreads();
            float acc[4][4] = {};
            #pragma unroll 8
            for (int d = 0; d < 64; d++) {
                float4 av = *(const float4*)&ta[d*68 + ty*4];
                float4 bv = *(const float4*)&tb[d*68 + tx*4];
                acc[0][0] = fmaf(av.x, bv.x, acc[0][0]);
                acc[0][1] = fmaf(av.x, bv.y, acc[0][1]);
                acc[0][2] = fmaf(av.x, bv.z, acc[0][2]);
                acc[0][3] = fmaf(av.x, bv.w, acc[0][3]);
                acc[1][0] = fmaf(av.y, bv.x, acc[1][0]);
                acc[1][1] = fmaf(av.y, bv.y, acc[1][1]);
                acc[1][2] = fmaf(av.y, bv.z, acc[1][2]);
                acc[1][3] = fmaf(av.y, bv.w, acc[1][3]);
                acc[2][0] = fmaf(av.z, bv.x, acc[2][0]);
                acc[2][1] = fmaf(av.z, bv.y, acc[2][1]);
                acc[2][2] = fmaf(av.z, bv.z, acc[2][2]);
                acc[2][3] = fmaf(av.z, bv.w, acc[2][3]);
                acc[3][0] = fmaf(av.w, bv.x, acc[3][0]);
                acc[3][1] = fmaf(av.w, bv.y, acc[3][1]);
                acc[3][2] = fmaf(av.w, bv.z, acc[3][2]);
                acc[3][3] = fmaf(av.w, bv.w, acc[3][3]);
            }
            #pragma unroll
            for (int i = 0; i < 4; i++) {
                float4 r; r.x = acc[i][0]; r.y = acc[i][1]; r.z = acc[i][2]; r.w = acc[i][3];
                *(float4*)&scb[(ty*4 + i)*SCST + mt*64 + tx*4] = r;
            }
            __syncthreads();
        }

        // ---- softmax over m for the 64 rows of scb ----
        for (int l = warp; l < 64; l += 8) {
            float* row = scb + l*SCST;
            float mx = -1e30f;
            for (int m = lane; m < SQ; m += 32) mx = fmaxf(mx, row[m]);
            #pragma unroll
            for (int o = 16; o; o >>= 1)
                mx = fmaxf(mx, __shfl_xor_sync(0xffffffffu, mx, o));
            float sum = 0.0f;
            for (int m = lane; m < SQ; m += 32) {
                float e = __expf(row[m] - mx);
                row[m] = e;
                sum += e;
            }
            #pragma unroll
            for (int o = 16; o; o >>= 1)
                sum += __shfl_xor_sync(0xffffffffu, sum, o);
            float inv = 1.0f / sum;
            for (int m = lane; m < SQ; m += 32) row[m] *= inv;
        }
        __syncthreads();

        // ---- GEMM2: u[i,d] = sum_m p[i,m] * v1[m,d], then v0 reduce ----
        float acc2[4][4] = {};
        for (int mt = 0; mt < 3; mt++) {
            for (int e = tid; e < 4096; e += 256) {
                int dd = e & 63, m = e >> 6;
                tb[m*68 + dd] = v1p[(mt*64 + m)*DK + dd];
            }
            __syncthreads();
            #pragma unroll 8
            for (int mm = 0; mm < 64; mm++) {
                float4 bv = *(const float4*)&tb[mm*68 + tx*4];
                float a0 = scb[(ty*4 + 0)*SCST + mt*64 + mm];
                float a1 = scb[(ty*4 + 1)*SCST + mt*64 + mm];
                float a2 = scb[(ty*4 + 2)*SCST + mt*64 + mm];
                float a3 = scb[(ty*4 + 3)*SCST + mt*64 + mm];
                acc2[0][0] = fmaf(a0, bv.x, acc2[0][0]);
                acc2[0][1] = fmaf(a0, bv.y, acc2[0][1]);
                acc2[0][2] = fmaf(a0, bv.z, acc2[0][2]);
                acc2[0][3] = fmaf(a0, bv.w, acc2[0][3]);
                acc2[1][0] = fmaf(a1, bv.x, acc2[1][0]);
                acc2[1][1] = fmaf(a1, bv.y, acc2[1][1]);
                acc2[1][2] = fmaf(a1, bv.z, acc2[1][2]);
                acc2[1][3] = fmaf(a1, bv.w, acc2[1][3]);
                acc2[2][0] = fmaf(a2, bv.x, acc2[2][0]);
                acc2[2][1] = fmaf(a2, bv.y, acc2[2][1]);
                acc2[2][2] = fmaf(a2, bv.z, acc2[2][2]);
                acc2[2][3] = fmaf(a2, bv.w, acc2[2][3]);
                acc2[3][0] = fmaf(a3, bv.x, acc2[3][0]);
                acc2[3][1] = fmaf(a3, bv.y, acc2[3][1]);
                acc2[3][2] = fmaf(a3, bv.z, acc2[3][2]);
                acc2[3][3] = fmaf(a3, bv.w, acc2[3][3]);
            }
            __syncthreads();
        }
        #pragma unroll
        for (int i = 0; i < 4; i++) {
            int l = lt*64 + ty*4 + i;
            float4 v0v = *(const float4*)&v0p[l*DK + tx*4];
            part[0] = fmaf(acc2[i][0], v0v.x, part[0]);
            part[1] = fmaf(acc2[i][1], v0v.y, part[1]);
            part[2] = fmaf(acc2[i][2], v0v.z, part[2]);
            part[3] = fmaf(acc2[i][3], v0v.w, part[3]);
        }
    }

    #pragma unroll
    for (int j = 0; j < 4; j++) atomicAdd(&sout[tx*4 + j], part[j]);
    __syncthreads();
    if (tid < 64) g_att[k*DM + h*DK + tid] = sout[tid];
}

// ---------------------------------------------------------------------------
extern "C" void kernel_launch(void* const* d_in, const int* in_sizes, int n_in,
                              void* d_out, int out_size)
{
    (void)in_sizes; (void)n_in; (void)out_size;

    const float* query = (const float*)d_in[0];
    const float* key   = (const float*)d_in[1];
    const float* value = (const float*)d_in[2];
    const float* Wq    = (const float*)d_in[3];
    const float* bq    = (const float*)d_in[4];
    const float* Wk0   = (const float*)d_in[5];
    const float* bk0   = (const float*)d_in[6];
    const float* Wk1   = (const float*)d_in[7];
    const float* bk1   = (const float*)d_in[8];
    const float* Wv0   = (const float*)d_in[9];
    const float* bv0   = (const float*)d_in[10];
    const float* Wv1   = (const float*)d_in[11];
    const float* bv1   = (const float*)d_in[12];
    const float* Wo    = (const float*)d_in[13];
    const float* bo    = (const float*)d_in[14];
    float* out = (float*)d_out;

    const size_t attn_smem = (size_t)(64*SCST + 2*64*68 + 128) * sizeof(float); // 85504 B
    cudaFuncSetAttribute(attn_kernel,
                         cudaFuncAttributeMaxDynamicSharedMemorySize,
                         (int)attn_smem);

    proj_kernel<<<dim3(3, 8, 5), 256>>>(query, key, value,
        Wq, bq, Wk0, bk0, Wk1, bk1, Wv0, bv0, Wv1, bv1, Wo, bo, out, 0);

    attn_kernel<<<dim3(SQ, NH), 256, attn_smem>>>();

    proj_kernel<<<dim3(3, 8, 1), 256>>>(query, key, value,
        Wq, bq, Wk0, bk0, Wk1, bk1, Wv0, bv0, Wv1, bv1, Wo, bo, out, 5);
}

// round 3
// speedup vs baseline: 3.5454x; 1.9992x over previous
#include <cuda_runtime.h>
#include <cstdint>

#define SQ     192
#define DM     512
#define NH     8
#define DK     64
#define SCST   196   // scores row stride
#define STA    68    // A / u tile stride
#define STB1   68    // k1 staging stride
#define STB2   72    // v1 staging stride

// Scratch (allocation-free rule: __device__ globals)
__device__ float g_q [NH*SQ*DK];
__device__ float g_k0[NH*SQ*DK];
__device__ float g_k1[NH*SQ*DK];
__device__ float g_v0[NH*SQ*DK];
__device__ float g_v1[NH*SQ*DK];
__device__ float g_att[SQ*DM];

__device__ __forceinline__ uint32_t f2tf(float x) {
    uint32_t r;
    asm("cvt.rna.tf32.f32 %0, %1;" : "=r"(r) : "f"(x));
    return r;
}

__device__ __forceinline__ void mma8(float* c, const uint32_t* a,
                                     uint32_t b0, uint32_t b1) {
    asm volatile(
        "mma.sync.aligned.m16n8k8.row.col.f32.tf32.tf32.f32 "
        "{%0,%1,%2,%3}, {%4,%5,%6,%7}, {%8,%9}, {%0,%1,%2,%3};"
        : "+f"(c[0]), "+f"(c[1]), "+f"(c[2]), "+f"(c[3])
        : "r"(a[0]), "r"(a[1]), "r"(a[2]), "r"(a[3]), "r"(b0), "r"(b1));
}

// ---------------------------------------------------------------------------
// Projection: Y = X @ W^T + b (same as R2 — 64x64 tile, K-chunk 32, float4,
// register double buffer). sel 0..4 split per head; sel 5 final output GEMM.
// ---------------------------------------------------------------------------
__global__ __launch_bounds__(256) void proj_kernel(
    const float* __restrict__ query, const float* __restrict__ keyi,
    const float* __restrict__ value,
    const float* __restrict__ Wq,  const float* __restrict__ bq,
    const float* __restrict__ Wk0, const float* __restrict__ bk0,
    const float* __restrict__ Wk1, const float* __restrict__ bk1,
    const float* __restrict__ Wv0, const float* __restrict__ bv0,
    const float* __restrict__ Wv1, const float* __restrict__ bv1,
    const float* __restrict__ Wo,  const float* __restrict__ bo,
    float* __restrict__ out, int base_sel)
{
    __shared__ __align__(16) float sx[32*68];
    __shared__ __align__(16) float sw[32*68];

    const int sel = base_sel + blockIdx.z;
    const float *X, *W, *B; float* Y; int split = 1;
    switch (sel) {
        case 0:  X = query; W = Wq;  B = bq;  Y = g_q;  break;
        case 1:  X = keyi;  W = Wk0; B = bk0; Y = g_k0; break;
        case 2:  X = keyi;  W = Wk1; B = bk1; Y = g_k1; break;
        case 3:  X = value; W = Wv0; B = bv0; Y = g_v0; break;
        case 4:  X = value; W = Wv1; B = bv1; Y = g_v1; break;
        default: X = g_att; W = Wo;  B = bo;  Y = out;  split = 0; break;
    }

    const int bs  = blockIdx.x * 64;
    const int bo_ = blockIdx.y * 64;
    const int tid = threadIdx.x;
    const int tx  = tid & 15;
    const int ty  = tid >> 4;

    float4 px[2], pw[2];
    #pragma unroll
    for (int u = 0; u < 2; u++) {
        int e = tid + u*256, c4 = e >> 6, r = e & 63;
        px[u] = *(const float4*)&X[(bs  + r)*DM + c4*4];
        pw[u] = *(const float4*)&W[(bo_ + r)*DM + c4*4];
    }

    float acc[4][4] = {};

    for (int ch = 0; ch < 16; ch++) {
        #pragma unroll
        for (int u = 0; u < 2; u++) {
            int e = tid + u*256, c4 = e >> 6, r = e & 63;
            float* dx = &sx[(c4*4)*68 + r];
            dx[0] = px[u].x; dx[68] = px[u].y; dx[136] = px[u].z; dx[204] = px[u].w;
            float* dw = &sw[(c4*4)*68 + r];
            dw[0] = pw[u].x; dw[68] = pw[u].y; dw[136] = pw[u].z; dw[204] = pw[u].w;
        }
        __syncthreads();
        if (ch < 15) {
            #pragma unroll
            for (int u = 0; u < 2; u++) {
                int e = tid + u*256, c4 = e >> 6, r = e & 63;
                px[u] = *(const float4*)&X[(bs  + r)*DM + (ch+1)*32 + c4*4];
                pw[u] = *(const float4*)&W[(bo_ + r)*DM + (ch+1)*32 + c4*4];
            }
        }
        #pragma unroll
        for (int kk = 0; kk < 32; kk++) {
            float4 av = *(const float4*)&sx[kk*68 + ty*4];
            float4 bv = *(const float4*)&sw[kk*68 + tx*4];
            acc[0][0] = fmaf(av.x, bv.x, acc[0][0]);
            acc[0][1] = fmaf(av.x, bv.y, acc[0][1]);
            acc[0][2] = fmaf(av.x, bv.z, acc[0][2]);
            acc[0][3] = fmaf(av.x, bv.w, acc[0][3]);
            acc[1][0] = fmaf(av.y, bv.x, acc[1][0]);
            acc[1][1] = fmaf(av.y, bv.y, acc[1][1]);
            acc[1][2] = fmaf(av.y, bv.z, acc[1][2]);
            acc[1][3] = fmaf(av.y, bv.w, acc[1][3]);
            acc[2][0] = fmaf(av.z, bv.x, acc[2][0]);
            acc[2][1] = fmaf(av.z, bv.y, acc[2][1]);
            acc[2][2] = fmaf(av.z, bv.z, acc[2][2]);
            acc[2][3] = fmaf(av.z, bv.w, acc[2][3]);
            acc[3][0] = fmaf(av.w, bv.x, acc[3][0]);
            acc[3][1] = fmaf(av.w, bv.y, acc[3][1]);
            acc[3][2] = fmaf(av.w, bv.z, acc[3][2]);
            acc[3][3] = fmaf(av.w, bv.w, acc[3][3]);
        }
        __syncthreads();
    }

    const int o4 = bo_ + tx*4;
    float4 bb = *(const float4*)&B[o4];
    #pragma unroll
    for (int i = 0; i < 4; i++) {
        int s = bs + ty*4 + i;
        float4 r;
        r.x = acc[i][0] + bb.x; r.y = acc[i][1] + bb.y;
        r.z = acc[i][2] + bb.z; r.w = acc[i][3] + bb.w;
        if (split) *(float4*)&Y[(o4 >> 6)*(SQ*DK) + s*DK + (o4 & 63)] = r;
        else       *(float4*)&Y[s*DM + o4] = r;
    }
}

// ---------------------------------------------------------------------------
// Attention core: one CTA per (h, k), 256 threads (8 warps), 2 CTAs/SM.
// tf32 mma.sync m16n8k8 for GEMM1 (scores) and GEMM2 (P @ v1).
// l-blocked 64 rows; SMEM: sS[64][196] + sA[64][68] + sB[64][72] + 128 floats.
// ---------------------------------------------------------------------------
__global__ __launch_bounds__(256, 2)
void attn_kernel()
{
    extern __shared__ __align__(16) float smem[];
    float* sS   = smem;                 // [64][SCST] scores / probs block
    float* sA   = sS + 64*SCST;         // [64][STA]  A (tf32) / u (fp32)
    float* sB   = sA + 64*STA;          // [64][STB2] k1 or v1 staging
    float* qsc  = sB + 64*STB2;         // [64]
    float* sout = qsc + 64;             // [64]

    const int k    = blockIdx.x;
    const int h    = blockIdx.y;
    const int tid  = threadIdx.x;
    const int warp = tid >> 5, lane = tid & 31;
    const int grp  = lane >> 2, tig = lane & 3;
    const int lw   = warp & 1;          // l-warp: rows lw*32..+31
    const int mw   = warp >> 1;         // GEMM1 col-warp (0..3) / GEMM2 d-warp

    const float* qp  = g_q  + (h*SQ + k) * DK;
    const float* k0p = g_k0 + h*SQ*DK;
    const float* k1p = g_k1 + h*SQ*DK;
    const float* v0p = g_v0 + h*SQ*DK;
    const float* v1p = g_v1 + h*SQ*DK;

    if (tid < 64) { qsc[tid] = qp[tid] * 0.125f; sout[tid] = 0.0f; }
    __syncthreads();

    float part = 0.0f;  // per-thread output partial for d = tid&63

    for (int lt = 0; lt < 3; lt++) {
        // ---- stage A block: sA[l][d] = tf32(qsc[d] * k0[lt*64+l][d]) ----
        for (int e = tid; e < 4096; e += 256) {
            int l = e >> 6, d = e & 63;
            sA[l*STA + d] =
                __uint_as_float(f2tf(qsc[d] * k0p[(lt*64 + l)*DK + d]));
        }

        // ---- GEMM1: sS[l, mt*64+j] = sum_d A[l,d] * k1[mt*64+j, d] ----
        for (int mt = 0; mt < 3; mt++) {
            for (int e = tid; e < 4096; e += 256) {
                int j = e >> 6, d = e & 63;
                sB[j*STB1 + d] =
                    __uint_as_float(f2tf(k1p[(mt*64 + j)*DK + d]));
            }
            __syncthreads();

            float c[2][2][4] = {};
            #pragma unroll
            for (int ks = 0; ks < 8; ks++) {
                const int kb = ks*8;
                uint32_t a[2][4];
                #pragma unroll
                for (int i = 0; i < 2; i++) {
                    int r = lw*32 + i*16 + grp;
                    a[i][0] = __float_as_uint(sA[r*STA + kb + tig]);
                    a[i][2] = __float_as_uint(sA[r*STA + kb + tig + 4]);
                    a[i][1] = __float_as_uint(sA[(r+8)*STA + kb + tig]);
                    a[i][3] = __float_as_uint(sA[(r+8)*STA + kb + tig + 4]);
                }
                #pragma unroll
                for (int j = 0; j < 2; j++) {
                    int mr = mw*16 + j*8 + grp;
                    uint32_t b0 = __float_as_uint(sB[mr*STB1 + kb + tig]);
                    uint32_t b1 = __float_as_uint(sB[mr*STB1 + kb + tig + 4]);
                    mma8(c[0][j], a[0], b0, b1);
                    mma8(c[1][j], a[1], b0, b1);
                }
            }
            #pragma unroll
            for (int i = 0; i < 2; i++) {
                int r = lw*32 + i*16 + grp;
                #pragma unroll
                for (int j = 0; j < 2; j++) {
                    int col = mt*64 + mw*16 + j*8 + tig*2;
                    *(float2*)&sS[r*SCST + col]     = make_float2(c[i][j][0], c[i][j][1]);
                    *(float2*)&sS[(r+8)*SCST + col] = make_float2(c[i][j][2], c[i][j][3]);
                }
            }
            __syncthreads();
        }

        // ---- softmax over m for the 64 rows; write back tf32-rounded ----
        for (int l = warp; l < 64; l += 8) {
            float* row = sS + l*SCST;
            float mx = -1e30f;
            #pragma unroll
            for (int m0 = 0; m0 < SQ; m0 += 32)
                mx = fmaxf(mx, row[m0 + lane]);
            #pragma unroll
            for (int o = 16; o; o >>= 1)
                mx = fmaxf(mx, __shfl_xor_sync(0xffffffffu, mx, o));
            float sum = 0.0f;
            #pragma unroll
            for (int m0 = 0; m0 < SQ; m0 += 32) {
                float e = __expf(row[m0 + lane] - mx);
                row[m0 + lane] = e;
                sum += e;
            }
            #pragma unroll
            for (int o = 16; o; o >>= 1)
                sum += __shfl_xor_sync(0xffffffffu, sum, o);
            float inv = 1.0f / sum;
            #pragma unroll
            for (int m0 = 0; m0 < SQ; m0 += 32)
                row[m0 + lane] = __uint_as_float(f2tf(row[m0 + lane] * inv));
        }
        __syncthreads();

        // ---- GEMM2: u[l,d] = sum_m P[l,m] * v1[m,d] ----
        float c2[2][2][4] = {};
        for (int mt = 0; mt < 3; mt++) {
            for (int e = tid; e < 4096; e += 256) {
                int m = e >> 6, d = e & 63;
                sB[m*STB2 + d] =
                    __uint_as_float(f2tf(v1p[(mt*64 + m)*DK + d]));
            }
            __syncthreads();
            #pragma unroll
            for (int ks = 0; ks < 8; ks++) {
                const int kk = mt*64 + ks*8;   // global m column in sS
                uint32_t b[2][2];
                #pragma unroll
                for (int j = 0; j < 2; j++) {
                    int dc = mw*16 + j*8 + grp;
                    b[j][0] = __float_as_uint(sB[(ks*8 + tig)*STB2 + dc]);
                    b[j][1] = __float_as_uint(sB[(ks*8 + tig + 4)*STB2 + dc]);
                }
                #pragma unroll
                for (int i = 0; i < 2; i++) {
                    int r = lw*32 + i*16 + grp;
                    uint32_t a[4];
                    a[0] = __float_as_uint(sS[r*SCST + kk + tig]);
                    a[2] = __float_as_uint(sS[r*SCST + kk + tig + 4]);
                    a[1] = __float_as_uint(sS[(r+8)*SCST + kk + tig]);
                    a[3] = __float_as_uint(sS[(r+8)*SCST + kk + tig + 4]);
                    mma8(c2[i][0], a, b[0][0], b[0][1]);
                    mma8(c2[i][1], a, b[1][0], b[1][1]);
                }
            }
            __syncthreads();
        }

        // ---- write u block to sA (reuse), then v0 elementwise reduce ----
        #pragma unroll
        for (int i = 0; i < 2; i++) {
            int r = lw*32 + i*16 + grp;
            #pragma unroll
            for (int j = 0; j < 2; j++) {
                int dc = mw*16 + j*8 + tig*2;
                *(float2*)&sA[r*STA + dc]     = make_float2(c2[i][j][0], c2[i][j][1]);
                *(float2*)&sA[(r+8)*STA + dc] = make_float2(c2[i][j][2], c2[i][j][3]);
            }
        }
        __syncthreads();
        {
            const int d = tid & 63, lg = tid >> 6;
            #pragma unroll
            for (int i = 0; i < 16; i++) {
                int l = lg*16 + i;
                part = fmaf(sA[l*STA + d], v0p[(lt*64 + l)*DK + d], part);
            }
        }
        __syncthreads();
    }

    atomicAdd(&sout[tid & 63], part);
    __syncthreads();
    if (tid < 64) g_att[k*DM + h*DK + tid] = sout[tid];
}

// ---------------------------------------------------------------------------
extern "C" void kernel_launch(void* const* d_in, const int* in_sizes, int n_in,
                              void* d_out, int out_size)
{
    (void)in_sizes; (void)n_in; (void)out_size;

    const float* query = (const float*)d_in[0];
    const float* key   = (const float*)d_in[1];
    const float* value = (const float*)d_in[2];
    const float* Wq    = (const float*)d_in[3];
    const float* bq    = (const float*)d_in[4];
    const float* Wk0   = (const float*)d_in[5];
    const float* bk0   = (const float*)d_in[6];
    const float* Wk1   = (const float*)d_in[7];
    const float* bk1   = (const float*)d_in[8];
    const float* Wv0   = (const float*)d_in[9];
    const float* bv0   = (const float*)d_in[10];
    const float* Wv1   = (const float*)d_in[11];
    const float* bv1   = (const float*)d_in[12];
    const float* Wo    = (const float*)d_in[13];
    const float* bo    = (const float*)d_in[14];
    float* out = (float*)d_out;

    const size_t attn_smem =
        (size_t)(64*SCST + 64*STA + 64*STB2 + 128) * sizeof(float); // 86528 B
    cudaFuncSetAttribute(attn_kernel,
                         cudaFuncAttributeMaxDynamicSharedMemorySize,
                         (int)attn_smem);

    proj_kernel<<<dim3(3, 8, 5), 256>>>(query, key, value,
        Wq, bq, Wk0, bk0, Wk1, bk1, Wv0, bv0, Wv1, bv1, Wo, bo, out, 0);

    attn_kernel<<<dim3(SQ, NH), 256, attn_smem>>>();

    proj_kernel<<<dim3(3, 8, 1), 256>>>(query, key, value,
        Wq, bq, Wk0, bk0, Wk1, bk1, Wv0, bv0, Wv1, bv1, Wo, bo, out, 5);
}